// round 16
// baseline (speedup 1.0000x reference)
#include <cuda_runtime.h>
#include <cstdint>

// Shapes fixed: value [8,4096,1024], last [8,1024], W [1024,1024], b [1024].
#define BB 8
#define TT 4096
#define HH 1024

#define RANGES 32              // T-splits per batch (fused kernel grid.x)
#define TR (TT / RANGES)       // 128 timesteps per block
#define NW 8                   // warps per fused block (256 threads)
#define NITER (TR / NW)        // 16 rows per warp (1 row per iteration)

#define OCH 128                // o-splits for query
#define OSEG (HH / OCH)        // 8

// -------- scratch (__device__ globals; no allocation allowed) --------
// g_q: zero at load; re-zeroed by the fused kernel's combine epilogue each
// run, so the atomicAdd accumulation in k_query starts from 0 every replay.
__device__ __align__(16) float g_q[BB * HH];
__device__ __align__(16) float g_cpart[BB * RANGES * HH]; // 1 MB
__device__ float g_mpart[BB * RANGES];
__device__ float g_spart[BB * RANGES];
__device__ int   g_cnt[BB];   // per-batch ticket counters (reset by combiner)

// ---------------------------------------------------------------------
// Kernel 1: q[b,h] += sum_{o in chunk} W[o,h]*last[b,o], accumulated with
// atomicAdd (coalesced REDG). grid (HH/128, OCH) = 1024 blocks, block 128.
// ---------------------------------------------------------------------
__global__ void k_query(const float* __restrict__ W,
                        const float* __restrict__ last) {
    __shared__ float ls[BB * OSEG];   // 64 floats
    const int oc = blockIdx.y;
    const int h  = blockIdx.x * 128 + threadIdx.x;

    if (threadIdx.x < BB * OSEG) {
        int b = threadIdx.x / OSEG, o = threadIdx.x % OSEG;
        ls[threadIdx.x] = last[b * HH + oc * OSEG + o];
    }
    __syncthreads();

    float wv[OSEG];
#pragma unroll
    for (int o = 0; o < OSEG; o++)
        wv[o] = W[(size_t)(oc * OSEG + o) * HH + h];

    float acc[BB];
#pragma unroll
    for (int b = 0; b < BB; b++) acc[b] = 0.f;
#pragma unroll
    for (int o = 0; o < OSEG; o++) {
#pragma unroll
        for (int b = 0; b < BB; b++)
            acc[b] = fmaf(wv[o], ls[b * OSEG + o], acc[b]);
    }
#pragma unroll
    for (int b = 0; b < BB; b++)
        atomicAdd(&g_q[b * HH + h], acc[b]);
}

// ---------------------------------------------------------------------
// Kernel 2: fused score + lazy-rescale online-softmax + context +
// last-block combine. DOUBLE-BUFFERED row loads on top of R15's lazy
// rescale: row t+1's 8 float4 loads issue BEFORE row t's dot/shfl/exp/
// accumulate, so the memory pipe stays fed through the math chain
// (sustained = max(load, compute) instead of load+compute). va[2][8]=64
// regs + cx[32] + ~20 = ~116 < 128 -> still 2 CTAs/SM. cx is a pure
// accumulator; wide rescale only on the warp-uniform rare overflow-
// headroom event (first iteration triggers it harmlessly from -1e30).
// Lane l, reg 4j+k maps to h = j*128 + l*4 + k.
// ---------------------------------------------------------------------
__global__ __launch_bounds__(256, 2)
void k_fused(const float* __restrict__ value, float* __restrict__ out) {
    __shared__ float4 q_sm[HH / 4];               // 4 KB
    __shared__ float4 red_c[(NW / 2) * (HH / 4)]; // 16 KB
    __shared__ float red_m[NW], red_s[NW];
    __shared__ float s_wgt[RANGES];
    __shared__ float s_invD;
    __shared__ int   s_ticket;

    const int b = blockIdx.y;
    const int r = blockIdx.x;
    const int tid = threadIdx.x;
    const int w = tid >> 5, l = tid & 31;

    const float4* vb = reinterpret_cast<const float4*>(value)
                     + ((size_t)b * TT + (size_t)r * TR) * (HH / 4);

    // Prefetch row 0 of this warp before anything else.
    float4 va[2][8];
    {
        const float4* p0 = vb + (size_t)w * (HH / 4) + l;
#pragma unroll
        for (int j = 0; j < 8; j++) va[0][j] = p0[j * 32];
    }

    q_sm[tid] = reinterpret_cast<const float4*>(g_q)[b * (HH / 4) + tid];
    __syncthreads();

    float cx[32];
#pragma unroll
    for (int i = 0; i < 32; i++) cx[i] = 0.f;
    float offset = -1e30f, sw = 0.f;

    for (int t = 0; t < NITER; t++) {
        const int cur = t & 1, nxt = cur ^ 1;
        // Issue next row's loads FIRST (independent of this row's math).
        if (t + 1 < NITER) {
            const float4* pn = vb + (size_t)((t + 1) * NW + w) * (HH / 4) + l;
#pragma unroll
            for (int j = 0; j < 8; j++) va[nxt][j] = pn[j * 32];
        }

        float d = 0.f;
#pragma unroll
        for (int j = 0; j < 8; j++) {
            float4 q = q_sm[j * 32 + l];
            d = fmaf(va[cur][j].x, q.x, d);
            d = fmaf(va[cur][j].y, q.y, d);
            d = fmaf(va[cur][j].z, q.z, d);
            d = fmaf(va[cur][j].w, q.w, d);
        }
#pragma unroll
        for (int off = 16; off; off >>= 1)
            d += __shfl_xor_sync(0xFFFFFFFFu, d, off);

        // Lazy rescale: only when a score threatens exp overflow headroom.
        if (d > offset + 60.f) {             // warp-uniform, rare
            const float f = __expf(offset - d);
            offset = d;
            sw *= f;
#pragma unroll
            for (int i = 0; i < 32; i++) cx[i] *= f;
        }
        const float ps = __expf(d - offset);
        sw += ps;
        // Pure accumulation: 32 independent FMAs, no serial cx chain.
#pragma unroll
        for (int j = 0; j < 8; j++) {
            cx[4*j+0] = fmaf(ps, va[cur][j].x, cx[4*j+0]);
            cx[4*j+1] = fmaf(ps, va[cur][j].y, cx[4*j+1]);
            cx[4*j+2] = fmaf(ps, va[cur][j].z, cx[4*j+2]);
            cx[4*j+3] = fmaf(ps, va[cur][j].w, cx[4*j+3]);
        }
    }
    float mw = offset;

    // Cross-warp tree merge of (m, s, c) online-softmax partials.
#pragma unroll
    for (int half = NW / 2; half >= 1; half >>= 1) {
        __syncthreads();
        if (w >= half && w < 2 * half) {
            const int slot = w - half;
#pragma unroll
            for (int j = 0; j < 8; j++)
                red_c[slot * (HH / 4) + j * 32 + l] =
                    make_float4(cx[4*j], cx[4*j+1], cx[4*j+2], cx[4*j+3]);
            if (l == 0) { red_m[slot] = mw; red_s[slot] = sw; }
        }
        __syncthreads();
        if (w < half) {
            const float mo = red_m[w], so = red_s[w];
            const float M  = fmaxf(mw, mo);
            const float ea = __expf(mw - M);
            const float eb = __expf(mo - M);
#pragma unroll
            for (int j = 0; j < 8; j++) {
                float4 o = red_c[w * (HH / 4) + j * 32 + l];
                cx[4*j+0] = cx[4*j+0] * ea + o.x * eb;
                cx[4*j+1] = cx[4*j+1] * ea + o.y * eb;
                cx[4*j+2] = cx[4*j+2] * ea + o.z * eb;
                cx[4*j+3] = cx[4*j+3] * ea + o.w * eb;
            }
            sw = sw * ea + so * eb;
            mw = M;
        }
    }

    if (w == 0) {
        float4* cp = reinterpret_cast<float4*>(g_cpart)
                   + (size_t)(b * RANGES + r) * (HH / 4);
#pragma unroll
        for (int j = 0; j < 8; j++)
            cp[j * 32 + l] = make_float4(cx[4*j], cx[4*j+1], cx[4*j+2], cx[4*j+3]);
        if (l == 0) {
            g_mpart[b * RANGES + r] = mw;
            g_spart[b * RANGES + r] = sw;
        }
    }
    __syncthreads();
    __threadfence();                 // publish this block's partials

    if (tid == 0) s_ticket = atomicAdd(&g_cnt[b], 1);
    __syncthreads();

    // ---- last block of this batch: combine the 32 partials -> out[b] ----
    if (s_ticket == RANGES - 1) {
        __threadfence();             // acquire others' partials

        if (tid < 32) {              // warp 0: merge weights into smem
            float m = g_mpart[b * RANGES + tid];
            float s = g_spart[b * RANGES + tid];
            float M = m;
#pragma unroll
            for (int off = 16; off; off >>= 1)
                M = fmaxf(M, __shfl_xor_sync(0xFFFFFFFFu, M, off));
            const float wg = __expf(m - M);
            float D = s * wg;
#pragma unroll
            for (int off = 16; off; off >>= 1)
                D += __shfl_xor_sync(0xFFFFFFFFu, D, off);
            s_wgt[tid] = wg;
            if (tid == 0) s_invD = 1.f / D;
        }
        __syncthreads();

        const float4* cp = reinterpret_cast<const float4*>(g_cpart)
                         + (size_t)b * RANGES * (HH / 4) + tid;
        float4 acc = make_float4(0.f, 0.f, 0.f, 0.f);
#pragma unroll
        for (int rr = 0; rr < RANGES; rr++) {
            const float wg = s_wgt[rr];
            float4 c4 = cp[(size_t)rr * (HH / 4)];
            acc.x = fmaf(wg, c4.x, acc.x);
            acc.y = fmaf(wg, c4.y, acc.y);
            acc.z = fmaf(wg, c4.z, acc.z);
            acc.w = fmaf(wg, c4.w, acc.w);
        }
        const float inv = s_invD;
        reinterpret_cast<float4*>(out)[b * (HH / 4) + tid] =
            make_float4(acc.x * inv, acc.y * inv, acc.z * inv, acc.w * inv);

        // Re-arm for the next graph replay: zero q[b], reset the counter.
        reinterpret_cast<float4*>(g_q)[b * (HH / 4) + tid] =
            make_float4(0.f, 0.f, 0.f, 0.f);
        __syncthreads();
        if (tid == 0) {
            __threadfence();
            g_cnt[b] = 0;
        }
    }
}

// ---------------------------------------------------------------------
extern "C" void kernel_launch(void* const* d_in, const int* in_sizes, int n_in,
                              void* d_out, int out_size) {
    const float* value = (const float*)d_in[0];  // [B,T,H]
    const float* last  = (const float*)d_in[1];  // [B,H]
    const float* W     = (const float*)d_in[2];  // [H,H]
    // d_in[3] = bias: constant per-batch shift in scores, cancels in softmax.
    float* out = (float*)d_out;                  // [B,1,H]
    (void)in_sizes; (void)n_in; (void)out_size;

    dim3 gq(HH / 128, OCH);
    k_query<<<gq, 128>>>(W, last);

    dim3 gf(RANGES, BB);
    k_fused<<<gf, 256>>>(value, out);
}

// round 17
// speedup vs baseline: 1.2508x; 1.2508x over previous
#include <cuda_runtime.h>
#include <cstdint>

// Shapes fixed: value [8,4096,1024], last [8,1024], W [1024,1024], b [1024].
#define BB 8
#define TT 4096
#define HH 1024

#define RANGES 32              // T-splits per batch (fused kernel grid.x)
#define TR (TT / RANGES)       // 128 timesteps per block
#define NW 8                   // warps per fused block (256 threads)
#define RPW 2                  // rows per warp per iteration
#define NITER (TR / (NW * RPW))// 8 iterations

#define OCH 128                // o-splits for query
#define OSEG (HH / OCH)        // 8

// -------- scratch (__device__ globals; no allocation allowed) --------
// g_q: zero at load; re-zeroed by the fused kernel's combine epilogue each
// run, so the atomicAdd accumulation in k_query starts from 0 every replay.
__device__ __align__(16) float g_q[BB * HH];
__device__ __align__(16) float g_cpart[BB * RANGES * HH]; // 1 MB
__device__ float g_mpart[BB * RANGES];
__device__ float g_spart[BB * RANGES];
__device__ int   g_cnt[BB];   // per-batch ticket counters (reset by combiner)

// ---------------------------------------------------------------------
// Kernel 1: q[b,h] += sum_{o in chunk} W[o,h]*last[b,o], accumulated with
// atomicAdd. VECTORIZED: each thread owns a float4 of h (4x fewer load
// requests for the same 4 MB of W). grid (HH/512, OCH) = 256 blocks.
// ---------------------------------------------------------------------
__global__ void k_query(const float* __restrict__ W,
                        const float* __restrict__ last) {
    __shared__ float ls[BB * OSEG];   // 64 floats
    const int oc = blockIdx.y;
    const int h4 = blockIdx.x * 128 + threadIdx.x;   // float4 column index

    if (threadIdx.x < BB * OSEG) {
        int b = threadIdx.x / OSEG, o = threadIdx.x % OSEG;
        ls[threadIdx.x] = last[b * HH + oc * OSEG + o];
    }
    __syncthreads();

    float4 wv[OSEG];
    const float4* W4 = reinterpret_cast<const float4*>(W);
#pragma unroll
    for (int o = 0; o < OSEG; o++)
        wv[o] = W4[(size_t)(oc * OSEG + o) * (HH / 4) + h4];

    float4 acc[BB];
#pragma unroll
    for (int b = 0; b < BB; b++) acc[b] = make_float4(0.f, 0.f, 0.f, 0.f);
#pragma unroll
    for (int o = 0; o < OSEG; o++) {
#pragma unroll
        for (int b = 0; b < BB; b++) {
            const float s = ls[b * OSEG + o];
            acc[b].x = fmaf(wv[o].x, s, acc[b].x);
            acc[b].y = fmaf(wv[o].y, s, acc[b].y);
            acc[b].z = fmaf(wv[o].z, s, acc[b].z);
            acc[b].w = fmaf(wv[o].w, s, acc[b].w);
        }
    }
#pragma unroll
    for (int b = 0; b < BB; b++) {
        float* dst = &g_q[b * HH + h4 * 4];
        atomicAdd(dst + 0, acc[b].x);
        atomicAdd(dst + 1, acc[b].y);
        atomicAdd(dst + 2, acc[b].z);
        atomicAdd(dst + 3, acc[b].w);
    }
}

// ---------------------------------------------------------------------
// Kernel 2: fused score + lazy-rescale online-softmax + context +
// last-block combine. EXACT R15 structure (the verified 30.7us fused):
// RPW=2, MLP=16, no register double-buffer (spills — proven R7/R16).
// Only change: value loads use __ldcs (evict-first streaming; value is
// read exactly once, keep it out of L2's way). cx is a pure accumulator;
// wide rescale only on the warp-uniform rare overflow-headroom event.
// Lane l, reg 4j+k maps to h = j*128 + l*4 + k.
// ---------------------------------------------------------------------
__global__ __launch_bounds__(256, 2)
void k_fused(const float* __restrict__ value, float* __restrict__ out) {
    __shared__ float4 q_sm[HH / 4];               // 4 KB
    __shared__ float4 red_c[(NW / 2) * (HH / 4)]; // 16 KB
    __shared__ float red_m[NW], red_s[NW];
    __shared__ float s_wgt[RANGES];
    __shared__ float s_invD;
    __shared__ int   s_ticket;

    const int b = blockIdx.y;
    const int r = blockIdx.x;
    const int tid = threadIdx.x;
    const int w = tid >> 5, l = tid & 31;

    q_sm[tid] = reinterpret_cast<const float4*>(g_q)[b * (HH / 4) + tid];
    __syncthreads();

    float cx[32];
#pragma unroll
    for (int i = 0; i < 32; i++) cx[i] = 0.f;
    float offset = -1e30f, sw = 0.f;

    const float4* vb = reinterpret_cast<const float4*>(value)
                     + ((size_t)b * TT + (size_t)r * TR) * (HH / 4);

    for (int it = 0; it < NITER; it++) {
        const int t0 = it * (NW * RPW) + w * RPW;
        const float4* p0 = vb + (size_t)t0 * (HH / 4) + l;
        const float4* p1 = p0 + (HH / 4);

        float4 v0[8], v1[8];
#pragma unroll
        for (int j = 0; j < 8; j++) v0[j] = __ldcs(p0 + j * 32);
#pragma unroll
        for (int j = 0; j < 8; j++) v1[j] = __ldcs(p1 + j * 32);

        float d0 = 0.f, d1 = 0.f;
#pragma unroll
        for (int j = 0; j < 8; j++) {
            float4 q = q_sm[j * 32 + l];
            d0 = fmaf(v0[j].x, q.x, d0); d0 = fmaf(v0[j].y, q.y, d0);
            d0 = fmaf(v0[j].z, q.z, d0); d0 = fmaf(v0[j].w, q.w, d0);
            d1 = fmaf(v1[j].x, q.x, d1); d1 = fmaf(v1[j].y, q.y, d1);
            d1 = fmaf(v1[j].z, q.z, d1); d1 = fmaf(v1[j].w, q.w, d1);
        }
#pragma unroll
        for (int off = 16; off; off >>= 1) {
            d0 += __shfl_xor_sync(0xFFFFFFFFu, d0, off);
            d1 += __shfl_xor_sync(0xFFFFFFFFu, d1, off);
        }

        // Lazy rescale: only when a score threatens exp overflow headroom.
        const float dmax = fmaxf(d0, d1);
        if (dmax > offset + 60.f) {          // warp-uniform, rare
            const float f = __expf(offset - dmax);
            offset = dmax;
            sw *= f;
#pragma unroll
            for (int i = 0; i < 32; i++) cx[i] *= f;
        }
        const float p0s = __expf(d0 - offset);
        const float p1s = __expf(d1 - offset);
        sw += p0s + p1s;
        // Pure accumulation: 64 independent FMAs, no serial cx chain.
#pragma unroll
        for (int j = 0; j < 8; j++) {
            cx[4*j+0] = fmaf(p0s, v0[j].x, cx[4*j+0]);
            cx[4*j+1] = fmaf(p0s, v0[j].y, cx[4*j+1]);
            cx[4*j+2] = fmaf(p0s, v0[j].z, cx[4*j+2]);
            cx[4*j+3] = fmaf(p0s, v0[j].w, cx[4*j+3]);
        }
#pragma unroll
        for (int j = 0; j < 8; j++) {
            cx[4*j+0] = fmaf(p1s, v1[j].x, cx[4*j+0]);
            cx[4*j+1] = fmaf(p1s, v1[j].y, cx[4*j+1]);
            cx[4*j+2] = fmaf(p1s, v1[j].z, cx[4*j+2]);
            cx[4*j+3] = fmaf(p1s, v1[j].w, cx[4*j+3]);
        }
    }
    float mw = offset;

    // Cross-warp tree merge of (m, s, c) online-softmax partials.
#pragma unroll
    for (int half = NW / 2; half >= 1; half >>= 1) {
        __syncthreads();
        if (w >= half && w < 2 * half) {
            const int slot = w - half;
#pragma unroll
            for (int j = 0; j < 8; j++)
                red_c[slot * (HH / 4) + j * 32 + l] =
                    make_float4(cx[4*j], cx[4*j+1], cx[4*j+2], cx[4*j+3]);
            if (l == 0) { red_m[slot] = mw; red_s[slot] = sw; }
        }
        __syncthreads();
        if (w < half) {
            const float mo = red_m[w], so = red_s[w];
            const float M  = fmaxf(mw, mo);
            const float ea = __expf(mw - M);
            const float eb = __expf(mo - M);
#pragma unroll
            for (int j = 0; j < 8; j++) {
                float4 o = red_c[w * (HH / 4) + j * 32 + l];
                cx[4*j+0] = cx[4*j+0] * ea + o.x * eb;
                cx[4*j+1] = cx[4*j+1] * ea + o.y * eb;
                cx[4*j+2] = cx[4*j+2] * ea + o.z * eb;
                cx[4*j+3] = cx[4*j+3] * ea + o.w * eb;
            }
            sw = sw * ea + so * eb;
            mw = M;
        }
    }

    if (w == 0) {
        float4* cp = reinterpret_cast<float4*>(g_cpart)
                   + (size_t)(b * RANGES + r) * (HH / 4);
#pragma unroll
        for (int j = 0; j < 8; j++)
            cp[j * 32 + l] = make_float4(cx[4*j], cx[4*j+1], cx[4*j+2], cx[4*j+3]);
        if (l == 0) {
            g_mpart[b * RANGES + r] = mw;
            g_spart[b * RANGES + r] = sw;
        }
    }
    __syncthreads();
    __threadfence();                 // publish this block's partials

    if (tid == 0) s_ticket = atomicAdd(&g_cnt[b], 1);
    __syncthreads();

    // ---- last block of this batch: combine the 32 partials -> out[b] ----
    if (s_ticket == RANGES - 1) {
        __threadfence();             // acquire others' partials

        if (tid < 32) {              // warp 0: merge weights into smem
            float m = g_mpart[b * RANGES + tid];
            float s = g_spart[b * RANGES + tid];
            float M = m;
#pragma unroll
            for (int off = 16; off; off >>= 1)
                M = fmaxf(M, __shfl_xor_sync(0xFFFFFFFFu, M, off));
            const float wg = __expf(m - M);
            float D = s * wg;
#pragma unroll
            for (int off = 16; off; off >>= 1)
                D += __shfl_xor_sync(0xFFFFFFFFu, D, off);
            s_wgt[tid] = wg;
            if (tid == 0) s_invD = 1.f / D;
        }
        __syncthreads();

        const float4* cp = reinterpret_cast<const float4*>(g_cpart)
                         + (size_t)b * RANGES * (HH / 4) + tid;
        float4 acc = make_float4(0.f, 0.f, 0.f, 0.f);
#pragma unroll
        for (int rr = 0; rr < RANGES; rr++) {
            const float wg = s_wgt[rr];
            float4 c4 = cp[(size_t)rr * (HH / 4)];
            acc.x = fmaf(wg, c4.x, acc.x);
            acc.y = fmaf(wg, c4.y, acc.y);
            acc.z = fmaf(wg, c4.z, acc.z);
            acc.w = fmaf(wg, c4.w, acc.w);
        }
        const float inv = s_invD;
        reinterpret_cast<float4*>(out)[b * (HH / 4) + tid] =
            make_float4(acc.x * inv, acc.y * inv, acc.z * inv, acc.w * inv);

        // Re-arm for the next graph replay: zero q[b], reset the counter.
        reinterpret_cast<float4*>(g_q)[b * (HH / 4) + tid] =
            make_float4(0.f, 0.f, 0.f, 0.f);
        __syncthreads();
        if (tid == 0) {
            __threadfence();
            g_cnt[b] = 0;
        }
    }
}

// ---------------------------------------------------------------------
extern "C" void kernel_launch(void* const* d_in, const int* in_sizes, int n_in,
                              void* d_out, int out_size) {
    const float* value = (const float*)d_in[0];  // [B,T,H]
    const float* last  = (const float*)d_in[1];  // [B,H]
    const float* W     = (const float*)d_in[2];  // [H,H]
    // d_in[3] = bias: constant per-batch shift in scores, cancels in softmax.
    float* out = (float*)d_out;                  // [B,1,H]
    (void)in_sizes; (void)n_in; (void)out_size;

    dim3 gq(HH / 512, OCH);
    k_query<<<gq, 128>>>(W, last);

    dim3 gf(RANGES, BB);
    k_fused<<<gf, 256>>>(value, out);
}